// round 6
// baseline (speedup 1.0000x reference)
#include <cuda_runtime.h>
#include <math.h>
#include <stdint.h>

#define S_ALL 2304
#define STXT  256
#define SIMG  2048
#define DM    3072
#define NH    24
#define HD    128

// ---------------- scratch (static device globals; no runtime allocation) ----
__device__ float g_Q [S_ALL * DM];
__device__ float g_K [S_ALL * DM];
__device__ float g_V [S_ALL * DM];
__device__ float g_O [S_ALL * DM];

__device__ __forceinline__ float to_tf32(float x) {
    uint32_t u;
    asm("cvt.rna.tf32.f32 %0, %1;" : "=r"(u) : "f"(x));
    return __uint_as_float(u);
}
__device__ __forceinline__ uint32_t to_tf32u(float x) {
    uint32_t u;
    asm("cvt.rna.tf32.f32 %0, %1;" : "=r"(u) : "f"(x));
    return u;
}

__device__ __forceinline__ void cp16(float* dst, const float* src) {
    uint32_t s = (uint32_t)__cvta_generic_to_shared(dst);
    asm volatile("cp.async.ca.shared.global [%0], [%1], 16;" :: "r"(s), "l"(src));
}
#define CP_COMMIT() asm volatile("cp.async.commit_group;")
#define CP_WAIT1()  asm volatile("cp.async.wait_group 1;")
#define CP_WAIT0()  asm volatile("cp.async.wait_group 0;")

// ============================================================================
// tf32 tensor-core GEMM, cp.async double-buffered.
// 128x128 block tile, 4 warps (2x2), warp tile 64x64, k-step 32.
// LDS/mma ratio = 1.0 (was 1.5 with 64x32 warp tiles).
// ============================================================================

#define PA 36    // As pitch: mod 32 == 4 -> conflict-free A-frag LDS
#define PB 136   // Bs pitch: mod 32 == 8 -> conflict-free B-frag LDS
#define GEMM_SMEM ((2 * 128 * PA + 2 * 32 * PB) * 4)

__device__ __forceinline__ void gemm128_tf32(
    const float* __restrict__ A, int lda,
    const float* __restrict__ B, int ldb,
    float* __restrict__ C, long ldc,
    int K, const float* __restrict__ bias, float scale)
{
    extern __shared__ float dsm[];
    float* AsB = dsm;                  // 2 stages of 128*PA
    float* BsB = dsm + 2 * 128 * PA;   // 2 stages of 32*PB

    const int tid  = threadIdx.x;
    const int warp = tid >> 5, lane = tid & 31;
    const int wm = (warp >> 1) * 64;   // warp row offset (0 / 64)
    const int wn = (warp & 1)  * 64;   // warp col offset (0 / 64)
    const int lr = lane >> 2, lc = lane & 3;

    // staging: A 128x32 (thread -> full row), B 32x128 (4 thr/row, 32 f each)
    const int am = tid;
    const int bk = tid >> 2, bn = (tid & 3) * 32;

    float acc[4][8][4];
#pragma unroll
    for (int mt = 0; mt < 4; mt++)
#pragma unroll
        for (int nt = 0; nt < 8; nt++)
#pragma unroll
            for (int r = 0; r < 4; r++) acc[mt][nt][r] = 0.f;

    auto issue = [&](int k0, int stage) {
        const float* Ag = A + (size_t)am * lda + k0;
        float* Ad = AsB + stage * 128 * PA + am * PA;
#pragma unroll
        for (int i = 0; i < 8; i++) cp16(Ad + i * 4, Ag + i * 4);
        const float* Bg = B + (size_t)(k0 + bk) * ldb + bn;
        float* Bd = BsB + stage * 32 * PB + bk * PB + bn;
#pragma unroll
        for (int i = 0; i < 8; i++) cp16(Bd + i * 4, Bg + i * 4);
        CP_COMMIT();
    };

    const int ntile = K / 32;
    issue(0, 0);

    for (int t = 0; t < ntile; t++) {
        const int cur = t & 1;
        if (t + 1 < ntile) { issue((t + 1) * 32, cur ^ 1); CP_WAIT1(); }
        else               { CP_WAIT0(); }
        __syncthreads();

        const float* As = AsB + cur * 128 * PA;
        const float* Bs = BsB + cur * 32 * PB;

#pragma unroll
        for (int kk = 0; kk < 32; kk += 8) {
            uint32_t a[4][4], b[8][2];
#pragma unroll
            for (int mt = 0; mt < 4; mt++) {
                int rb = wm + mt * 16;
                a[mt][0] = to_tf32u(As[(rb + lr)     * PA + kk + lc]);
                a[mt][1] = to_tf32u(As[(rb + lr + 8) * PA + kk + lc]);
                a[mt][2] = to_tf32u(As[(rb + lr)     * PA + kk + lc + 4]);
                a[mt][3] = to_tf32u(As[(rb + lr + 8) * PA + kk + lc + 4]);
            }
#pragma unroll
            for (int nt = 0; nt < 8; nt++) {
                int cb = wn + nt * 8;
                b[nt][0] = to_tf32u(Bs[(kk + lc)     * PB + cb + lr]);
                b[nt][1] = to_tf32u(Bs[(kk + lc + 4) * PB + cb + lr]);
            }
#pragma unroll
            for (int mt = 0; mt < 4; mt++)
#pragma unroll
                for (int nt = 0; nt < 8; nt++) {
                    asm("mma.sync.aligned.m16n8k8.row.col.f32.tf32.tf32.f32 "
                        "{%0,%1,%2,%3}, {%4,%5,%6,%7}, {%8,%9}, {%0,%1,%2,%3};"
                        : "+f"(acc[mt][nt][0]), "+f"(acc[mt][nt][1]),
                          "+f"(acc[mt][nt][2]), "+f"(acc[mt][nt][3])
                        : "r"(a[mt][0]), "r"(a[mt][1]), "r"(a[mt][2]), "r"(a[mt][3]),
                          "r"(b[nt][0]), "r"(b[nt][1]));
                }
        }
        __syncthreads();
    }

#pragma unroll
    for (int mt = 0; mt < 4; mt++) {
        int row = wm + mt * 16 + lr;
#pragma unroll
        for (int nt = 0; nt < 8; nt++) {
            int col = wn + nt * 8 + 2 * lc;
            float b0 = bias ? bias[col]     : 0.f;
            float b1 = bias ? bias[col + 1] : 0.f;
            C[(size_t)row * ldc + col]           = acc[mt][nt][0] * scale + b0;
            C[(size_t)row * ldc + col + 1]       = acc[mt][nt][1] * scale + b1;
            C[(size_t)(row + 8) * ldc + col]     = acc[mt][nt][2] * scale + b0;
            C[(size_t)(row + 8) * ldc + col + 1] = acc[mt][nt][3] * scale + b1;
        }
    }
}

// ---- QKV projection (merged: z selects q/k/v) -------------------------------
__global__ __launch_bounds__(128) void k_qkv(
    const float* __restrict__ hid, const float* __restrict__ enc,
    const float* __restrict__ wq,  const float* __restrict__ wk,
    const float* __restrict__ wv,
    const float* __restrict__ wqa, const float* __restrict__ wka,
    const float* __restrict__ wva,
    const float* __restrict__ bqa, const float* __restrict__ bka,
    const float* __restrict__ bva)
{
    const int which = blockIdx.z;
    float* out = (which == 0) ? g_Q : (which == 1) ? g_K : g_V;
    const float* W    = (which == 0) ? wq  : (which == 1) ? wk  : wv;
    const float* Wadd = (which == 0) ? wqa : (which == 1) ? wka : wva;
    const float* badd = (which == 0) ? bqa : (which == 1) ? bka : bva;

    const int n0 = blockIdx.x * 128;
    const int m0 = blockIdx.y * 128;
    const bool is_enc = (m0 < STXT);
    const float* A = is_enc ? (enc + (size_t)m0 * DM)
                            : (hid + (size_t)(m0 - STXT) * DM);
    const float* B = (is_enc ? Wadd : W) + n0;
    gemm128_tf32(A, DM, B, DM,
                 out + (size_t)m0 * DM + n0, DM, DM,
                 is_enc ? (badd + n0) : nullptr, 1.0f);
}

// ---- per-(token, head) RMSNorm + RoPE, in place (z: 0=Q, 1=K) ---------------
__global__ __launch_bounds__(128) void k_normrope(
    const float* __restrict__ nq,  const float* __restrict__ naq,
    const float* __restrict__ nk,  const float* __restrict__ nak,
    const float* __restrict__ cosb, const float* __restrict__ sinb)
{
    const int r = blockIdx.x;
    const int h = blockIdx.y;
    const int sel = blockIdx.z;
    const int d = threadIdx.x;

    float* buf = sel ? g_K : g_Q;
    float x = buf[(size_t)r * DM + h * HD + d];

    float ss = x * x;
#pragma unroll
    for (int o = 16; o > 0; o >>= 1) ss += __shfl_xor_sync(0xffffffffu, ss, o);
    __shared__ float wsum[4];
    if ((d & 31) == 0) wsum[d >> 5] = ss;
    __syncthreads();
    float var = (wsum[0] + wsum[1] + wsum[2] + wsum[3]) * (1.0f / HD);
    float rs = rsqrtf(var + 1e-6f);

    const float* gm = sel ? ((r < STXT) ? nak : nk)
                          : ((r < STXT) ? naq : nq);
    float xn = x * rs * gm[d];

    float xp  = __shfl_xor_sync(0xffffffffu, xn, 1);
    float c   = cosb[r * HD + d];
    float s   = sinb[r * HD + d];
    float rot = (d & 1) ? xp : -xp;
    float y   = xn * c + rot * s;

    buf[(size_t)r * DM + h * HD + d] = y;
}

// ============================================================================
// Fused flash attention, cp.async double-buffered K/V chunks (64 x 128 each).
// One block = (head, 128 q-rows). 8 warps; each warp owns 16 complete rows.
// ============================================================================

#define PQ 132   // Q/K smem pitch (mod 32 == 4)
#define PV 136   // V smem pitch (mod 32 == 8)
#define FLASH_SMEM ((128 * PQ + 2 * 64 * PQ + 2 * 64 * PV) * 4)

__global__ __launch_bounds__(256) void k_flash()
{
    extern __shared__ float sm[];
    float* Qs  = sm;                          // 128 x PQ (tf32, pre-scaled)
    float* KsB = sm + 128 * PQ;               // 2 stages of 64 x PQ
    float* VsB = KsB + 2 * 64 * PQ;           // 2 stages of 64 x PV

    const int tid  = threadIdx.x;
    const int warp = tid >> 5, lane = tid & 31;
    const int lr = lane >> 2, lc = lane & 3;
    const int h  = blockIdx.y;
    const int m0 = blockIdx.x * 128;
    const float scale = 0.088388347648318447f; // 1/sqrt(128)

    // load Q tile (pre-scaled, tf32): 128 rows x 128 cols
    for (int i = tid; i < 128 * 32; i += 256) {
        int row = i >> 5, c4 = (i & 31) * 4;
        float4 v = *(const float4*)(g_Q + (size_t)(m0 + row) * DM + h * HD + c4);
        float4 w;
        w.x = to_tf32(v.x * scale); w.y = to_tf32(v.y * scale);
        w.z = to_tf32(v.z * scale); w.w = to_tf32(v.w * scale);
        *(float4*)&Qs[row * PQ + c4] = w;
    }

    float m_r0 = -1e30f, m_r1 = -1e30f;
    float l_r0 = 0.f,    l_r1 = 0.f;
    float O[16][4];
#pragma unroll
    for (int i = 0; i < 16; i++)
#pragma unroll
        for (int j = 0; j < 4; j++) O[i][j] = 0.f;

    const int rb = warp * 16;
    const int srcA = (lane & 28) | (lc >> 1);
    const int srcB = srcA + 2;
    const bool odd = lc & 1;

    // 64 rows x 128 floats per tensor = 2048 16B-segments; 8 per thread each.
    auto issue_chunk = [&](int c, int stage) {
        const int s0 = c * 64;
        float* Kd = KsB + stage * 64 * PQ;
        float* Vd = VsB + stage * 64 * PV;
#pragma unroll
        for (int q = 0; q < 8; q++) {
            int idx = tid + q * 256;            // 0..2047
            int row = idx >> 5;                 // 0..63
            int off = (idx & 31) * 4;           // 0..124
            const float* gk = g_K + (size_t)(s0 + row) * DM + h * HD + off;
            const float* gv = g_V + (size_t)(s0 + row) * DM + h * HD + off;
            cp16(&Kd[row * PQ + off], gk);
            cp16(&Vd[row * PV + off], gv);
        }
        CP_COMMIT();
    };

    issue_chunk(0, 0);

    const int NCH = S_ALL / 64;
    for (int c = 0; c < NCH; c++) {
        const int cur = c & 1;
        if (c + 1 < NCH) { issue_chunk(c + 1, cur ^ 1); CP_WAIT1(); }
        else             { CP_WAIT0(); }
        __syncthreads();

        float* Ks = KsB + cur * 64 * PQ;
        float* Vs = VsB + cur * 64 * PV;

        // in-place tf32 conversion: full 64 x 128 (32 K + 32 V floats / thread)
        {
            int row = tid >> 2, col = (tid & 3) * 32;
            float* pk = &Ks[row * PQ + col];
            float* pv = &Vs[row * PV + col];
#pragma unroll
            for (int i = 0; i < 32; i++) pk[i] = to_tf32(pk[i]);
#pragma unroll
            for (int i = 0; i < 32; i++) pv[i] = to_tf32(pv[i]);
        }
        __syncthreads();

        // ---- S = Q K^T for this chunk: warp rows [rb, rb+16), cols [0,64)
        float sacc[8][4];
#pragma unroll
        for (int nt = 0; nt < 8; nt++)
#pragma unroll
            for (int r = 0; r < 4; r++) sacc[nt][r] = 0.f;

#pragma unroll
        for (int kk = 0; kk < HD; kk += 8) {
            uint32_t a0 = __float_as_uint(Qs[(rb + lr)     * PQ + kk + lc]);
            uint32_t a1 = __float_as_uint(Qs[(rb + lr + 8) * PQ + kk + lc]);
            uint32_t a2 = __float_as_uint(Qs[(rb + lr)     * PQ + kk + lc + 4]);
            uint32_t a3 = __float_as_uint(Qs[(rb + lr + 8) * PQ + kk + lc + 4]);
#pragma unroll
            for (int nt = 0; nt < 8; nt++) {
                uint32_t b0 = __float_as_uint(Ks[(nt * 8 + lr) * PQ + kk + lc]);
                uint32_t b1 = __float_as_uint(Ks[(nt * 8 + lr) * PQ + kk + lc + 4]);
                asm("mma.sync.aligned.m16n8k8.row.col.f32.tf32.tf32.f32 "
                    "{%0,%1,%2,%3}, {%4,%5,%6,%7}, {%8,%9}, {%0,%1,%2,%3};"
                    : "+f"(sacc[nt][0]), "+f"(sacc[nt][1]),
                      "+f"(sacc[nt][2]), "+f"(sacc[nt][3])
                    : "r"(a0), "r"(a1), "r"(a2), "r"(a3), "r"(b0), "r"(b1));
            }
        }

        // ---- online softmax (warp-local)
        float cm0 = -1e30f, cm1 = -1e30f;
#pragma unroll
        for (int nt = 0; nt < 8; nt++) {
            cm0 = fmaxf(cm0, fmaxf(sacc[nt][0], sacc[nt][1]));
            cm1 = fmaxf(cm1, fmaxf(sacc[nt][2], sacc[nt][3]));
        }
        cm0 = fmaxf(cm0, __shfl_xor_sync(0xffffffffu, cm0, 1));
        cm0 = fmaxf(cm0, __shfl_xor_sync(0xffffffffu, cm0, 2));
        cm1 = fmaxf(cm1, __shfl_xor_sync(0xffffffffu, cm1, 1));
        cm1 = fmaxf(cm1, __shfl_xor_sync(0xffffffffu, cm1, 2));

        float mn0 = fmaxf(m_r0, cm0), mn1 = fmaxf(m_r1, cm1);
        float al0 = __expf(m_r0 - mn0), al1 = __expf(m_r1 - mn1);
        m_r0 = mn0; m_r1 = mn1;

        float cs0 = 0.f, cs1 = 0.f;
#pragma unroll
        for (int nt = 0; nt < 8; nt++) {
            float p0 = to_tf32(__expf(sacc[nt][0] - mn0));
            float p1 = to_tf32(__expf(sacc[nt][1] - mn0));
            float p2 = to_tf32(__expf(sacc[nt][2] - mn1));
            float p3 = to_tf32(__expf(sacc[nt][3] - mn1));
            sacc[nt][0] = p0; sacc[nt][1] = p1; sacc[nt][2] = p2; sacc[nt][3] = p3;
            cs0 += p0 + p1; cs1 += p2 + p3;
        }
        cs0 += __shfl_xor_sync(0xffffffffu, cs0, 1);
        cs0 += __shfl_xor_sync(0xffffffffu, cs0, 2);
        cs1 += __shfl_xor_sync(0xffffffffu, cs1, 1);
        cs1 += __shfl_xor_sync(0xffffffffu, cs1, 2);
        l_r0 = l_r0 * al0 + cs0;
        l_r1 = l_r1 * al1 + cs1;

#pragma unroll
        for (int nt2 = 0; nt2 < 16; nt2++) {
            O[nt2][0] *= al0; O[nt2][1] *= al0;
            O[nt2][2] *= al1; O[nt2][3] *= al1;
        }

        // ---- O += P V : C-frag -> A-frag via register shuffles
#pragma unroll
        for (int ks = 0; ks < 8; ks++) {
            float c0 = sacc[ks][0], c1 = sacc[ks][1];
            float c2 = sacc[ks][2], c3 = sacc[ks][3];
            float v00 = __shfl_sync(0xffffffffu, c0, srcA);
            float v01 = __shfl_sync(0xffffffffu, c1, srcA);
            float v10 = __shfl_sync(0xffffffffu, c2, srcA);
            float v11 = __shfl_sync(0xffffffffu, c3, srcA);
            float w00 = __shfl_sync(0xffffffffu, c0, srcB);
            float w01 = __shfl_sync(0xffffffffu, c1, srcB);
            float w10 = __shfl_sync(0xffffffffu, c2, srcB);
            float w11 = __shfl_sync(0xffffffffu, c3, srcB);
            uint32_t a0 = __float_as_uint(odd ? v01 : v00);
            uint32_t a1 = __float_as_uint(odd ? v11 : v10);
            uint32_t a2 = __float_as_uint(odd ? w01 : w00);
            uint32_t a3 = __float_as_uint(odd ? w11 : w10);
#pragma unroll
            for (int nt2 = 0; nt2 < 16; nt2++) {
                uint32_t b0 = __float_as_uint(Vs[(ks * 8 + lc)     * PV + nt2 * 8 + lr]);
                uint32_t b1 = __float_as_uint(Vs[(ks * 8 + lc + 4) * PV + nt2 * 8 + lr]);
                asm("mma.sync.aligned.m16n8k8.row.col.f32.tf32.tf32.f32 "
                    "{%0,%1,%2,%3}, {%4,%5,%6,%7}, {%8,%9}, {%0,%1,%2,%3};"
                    : "+f"(O[nt2][0]), "+f"(O[nt2][1]),
                      "+f"(O[nt2][2]), "+f"(O[nt2][3])
                    : "r"(a0), "r"(a1), "r"(a2), "r"(a3), "r"(b0), "r"(b1));
            }
        }
        __syncthreads();
    }

    // ---- epilogue
    float i0 = 1.0f / l_r0, i1 = 1.0f / l_r1;
    const int row0 = m0 + rb + lr;
#pragma unroll
    for (int nt2 = 0; nt2 < 16; nt2++) {
        int col = h * HD + nt2 * 8 + 2 * lc;
        g_O[(size_t)row0 * DM + col]           = O[nt2][0] * i0;
        g_O[(size_t)row0 * DM + col + 1]       = O[nt2][1] * i0;
        g_O[(size_t)(row0 + 8) * DM + col]     = O[nt2][2] * i1;
        g_O[(size_t)(row0 + 8) * DM + col + 1] = O[nt2][3] * i1;
    }
}

// ---- output projections ------------------------------------------------------
__global__ __launch_bounds__(128) void k_outproj(
    const float* __restrict__ w_out, const float* __restrict__ b_out,
    const float* __restrict__ w_ao,  const float* __restrict__ b_ao,
    float* __restrict__ outbuf)
{
    const int n0 = blockIdx.x * 128;
    const int m0 = blockIdx.y * 128;
    const bool is_enc = (m0 < STXT);
    const float* B    = (is_enc ? w_ao : w_out) + n0;
    const float* bias = (is_enc ? b_ao : b_out) + n0;
    float* out = is_enc ? (outbuf + (size_t)SIMG * DM + (size_t)m0 * DM)
                        : (outbuf + (size_t)(m0 - STXT) * DM);
    gemm128_tf32(g_O + (size_t)m0 * DM, DM, B, DM,
                 out + n0, DM, DM, bias, 1.0f);
}

// ============================================================================
extern "C" void kernel_launch(void* const* d_in, const int* in_sizes, int n_in,
                              void* d_out, int out_size)
{
    const float* hid  = (const float*)d_in[0];
    const float* enc  = (const float*)d_in[1];
    const float* cosb = (const float*)d_in[2];
    const float* sinb = (const float*)d_in[3];
    const float* wq   = (const float*)d_in[4];
    const float* wk   = (const float*)d_in[5];
    const float* wv   = (const float*)d_in[6];
    const float* wqa  = (const float*)d_in[7];
    const float* wka  = (const float*)d_in[8];
    const float* wva  = (const float*)d_in[9];
    const float* bqa  = (const float*)d_in[10];
    const float* bka  = (const float*)d_in[11];
    const float* bva  = (const float*)d_in[12];
    const float* nq   = (const float*)d_in[13];
    const float* nk   = (const float*)d_in[14];
    const float* naq  = (const float*)d_in[15];
    const float* nak  = (const float*)d_in[16];
    const float* wout = (const float*)d_in[17];
    const float* bout = (const float*)d_in[18];
    const float* wao  = (const float*)d_in[19];
    const float* bao  = (const float*)d_in[20];
    float* out = (float*)d_out;

    cudaFuncSetAttribute(k_qkv,     cudaFuncAttributeMaxDynamicSharedMemorySize, GEMM_SMEM);
    cudaFuncSetAttribute(k_outproj, cudaFuncAttributeMaxDynamicSharedMemorySize, GEMM_SMEM);
    cudaFuncSetAttribute(k_flash,   cudaFuncAttributeMaxDynamicSharedMemorySize, FLASH_SMEM);

    dim3 qkv_grid(DM / 128, S_ALL / 128, 3);        // 24 x 18 x 3
    k_qkv<<<qkv_grid, 128, GEMM_SMEM>>>(hid, enc, wq, wk, wv,
                                        wqa, wka, wva, bqa, bka, bva);

    dim3 nr_grid(S_ALL, NH, 2);
    k_normrope<<<nr_grid, 128>>>(nq, naq, nk, nak, cosb, sinb);

    dim3 fl_grid(S_ALL / 128, NH);                  // 18 x 24
    k_flash<<<fl_grid, 256, FLASH_SMEM>>>();

    dim3 gemm_grid(DM / 128, S_ALL / 128);          // 24 x 18
    k_outproj<<<gemm_grid, 128, GEMM_SMEM>>>(wout, bout, wao, bao, out);
}

// round 7
// speedup vs baseline: 1.2748x; 1.2748x over previous
#include <cuda_runtime.h>
#include <math.h>
#include <stdint.h>

#define S_ALL 2304
#define STXT  256
#define SIMG  2048
#define DM    3072
#define NH    24
#define HD    128

// ---------------- scratch (static device globals; no runtime allocation) ----
__device__ float g_Q [S_ALL * DM];
__device__ float g_K [S_ALL * DM];
__device__ float g_V [S_ALL * DM];
__device__ float g_O [S_ALL * DM];

__device__ __forceinline__ float to_tf32(float x) {
    uint32_t u;
    asm("cvt.rna.tf32.f32 %0, %1;" : "=r"(u) : "f"(x));
    return __uint_as_float(u);
}
__device__ __forceinline__ uint32_t to_tf32u(float x) {
    uint32_t u;
    asm("cvt.rna.tf32.f32 %0, %1;" : "=r"(u) : "f"(x));
    return u;
}

__device__ __forceinline__ void cp16(float* dst, const float* src) {
    uint32_t s = (uint32_t)__cvta_generic_to_shared(dst);
    asm volatile("cp.async.cg.shared.global [%0], [%1], 16;" :: "r"(s), "l"(src));
}
#define CP_COMMIT() asm volatile("cp.async.commit_group;")
#define CP_WAIT1()  asm volatile("cp.async.wait_group 1;")
#define CP_WAIT0()  asm volatile("cp.async.wait_group 0;")

// ============================================================================
// tf32 tensor-core GEMM core (R5 config): 128x128 block tile, 8 warps (2x4),
// warp tile 64x32, k-step 32, cp.async double-buffered. Leaves acc in regs.
// ============================================================================

#define PA 36    // As pitch: mod 32 == 4 -> conflict-free A-frag LDS
#define PB 136   // Bs pitch: mod 32 == 8 -> conflict-free B-frag LDS
#define PE 132   // epilogue staging pitch
#define GEMM_SMEM ((2 * 128 * PA + 2 * 32 * PB) * 4)

__device__ __forceinline__ void gemm_core(
    const float* __restrict__ A, int lda,
    const float* __restrict__ B, int ldb,
    int K, float acc[4][4][4])
{
    extern __shared__ float dsm[];
    float* AsB = dsm;                  // 2 stages of 128*PA
    float* BsB = dsm + 2 * 128 * PA;   // 2 stages of 32*PB

    const int tid  = threadIdx.x;
    const int warp = tid >> 5, lane = tid & 31;
    const int wm = (warp >> 2) * 64;
    const int wn = (warp & 3)  * 32;
    const int lr = lane >> 2, lc = lane & 3;

    const int am = tid >> 1, ak = (tid & 1) * 16;
    const int bk = tid >> 3, bn = (tid & 7) * 16;

#pragma unroll
    for (int mt = 0; mt < 4; mt++)
#pragma unroll
        for (int nt = 0; nt < 4; nt++)
#pragma unroll
            for (int r = 0; r < 4; r++) acc[mt][nt][r] = 0.f;

    auto issue = [&](int k0, int stage) {
        const float* Ag = A + (size_t)am * lda + k0 + ak;
        float* Ad = AsB + stage * 128 * PA + am * PA + ak;
#pragma unroll
        for (int i = 0; i < 4; i++) cp16(Ad + i * 4, Ag + i * 4);
        const float* Bg = B + (size_t)(k0 + bk) * ldb + bn;
        float* Bd = BsB + stage * 32 * PB + bk * PB + bn;
#pragma unroll
        for (int i = 0; i < 4; i++) cp16(Bd + i * 4, Bg + i * 4);
        CP_COMMIT();
    };

    const int ntile = K / 32;
    issue(0, 0);

    for (int t = 0; t < ntile; t++) {
        const int cur = t & 1;
        if (t + 1 < ntile) { issue((t + 1) * 32, cur ^ 1); CP_WAIT1(); }
        else               { CP_WAIT0(); }
        __syncthreads();

        const float* As = AsB + cur * 128 * PA;
        const float* Bs = BsB + cur * 32 * PB;

#pragma unroll
        for (int kk = 0; kk < 32; kk += 8) {
            uint32_t a[4][4], b[4][2];
#pragma unroll
            for (int mt = 0; mt < 4; mt++) {
                int rb = wm + mt * 16;
                a[mt][0] = to_tf32u(As[(rb + lr)     * PA + kk + lc]);
                a[mt][1] = to_tf32u(As[(rb + lr + 8) * PA + kk + lc]);
                a[mt][2] = to_tf32u(As[(rb + lr)     * PA + kk + lc + 4]);
                a[mt][3] = to_tf32u(As[(rb + lr + 8) * PA + kk + lc + 4]);
            }
#pragma unroll
            for (int nt = 0; nt < 4; nt++) {
                int cb = wn + nt * 8;
                b[nt][0] = to_tf32u(Bs[(kk + lc)     * PB + cb + lr]);
                b[nt][1] = to_tf32u(Bs[(kk + lc + 4) * PB + cb + lr]);
            }
#pragma unroll
            for (int mt = 0; mt < 4; mt++)
#pragma unroll
                for (int nt = 0; nt < 4; nt++) {
                    asm("mma.sync.aligned.m16n8k8.row.col.f32.tf32.tf32.f32 "
                        "{%0,%1,%2,%3}, {%4,%5,%6,%7}, {%8,%9}, {%0,%1,%2,%3};"
                        : "+f"(acc[mt][nt][0]), "+f"(acc[mt][nt][1]),
                          "+f"(acc[mt][nt][2]), "+f"(acc[mt][nt][3])
                        : "r"(a[mt][0]), "r"(a[mt][1]), "r"(a[mt][2]), "r"(a[mt][3]),
                          "r"(b[nt][0]), "r"(b[nt][1]));
                }
        }
        __syncthreads();
    }
}

// ---- QKV projection + fused RMSNorm/RoPE epilogue for Q and K ---------------
// One 128-wide N tile == one head, so full head vectors live in this block.
__global__ __launch_bounds__(256) void k_qkv(
    const float* __restrict__ hid, const float* __restrict__ enc,
    const float* __restrict__ wq,  const float* __restrict__ wk,
    const float* __restrict__ wv,
    const float* __restrict__ wqa, const float* __restrict__ wka,
    const float* __restrict__ wva,
    const float* __restrict__ bqa, const float* __restrict__ bka,
    const float* __restrict__ bva,
    const float* __restrict__ nq,  const float* __restrict__ naq,
    const float* __restrict__ nk,  const float* __restrict__ nak,
    const float* __restrict__ cosb, const float* __restrict__ sinb)
{
    extern __shared__ float dsm[];
    const int which = blockIdx.z;
    const float* W    = (which == 0) ? wq  : (which == 1) ? wk  : wv;
    const float* Wadd = (which == 0) ? wqa : (which == 1) ? wka : wva;
    const float* badd = (which == 0) ? bqa : (which == 1) ? bka : bva;

    const int n0 = blockIdx.x * 128;
    const int m0 = blockIdx.y * 128;
    const bool is_enc = (m0 < STXT);
    const float* A = is_enc ? (enc + (size_t)m0 * DM)
                            : (hid + (size_t)(m0 - STXT) * DM);
    const float* B = (is_enc ? Wadd : W) + n0;

    float acc[4][4][4];
    gemm_core(A, DM, B, DM, DM, acc);

    const int tid  = threadIdx.x;
    const int warp = tid >> 5, lane = tid & 31;
    const int wm = (warp >> 2) * 64;
    const int wn = (warp & 3)  * 32;
    const int lr = lane >> 2, lc = lane & 3;

    if (which == 2) {
        // V: plain epilogue (bias on encoder rows)
#pragma unroll
        for (int mt = 0; mt < 4; mt++) {
            int row = wm + mt * 16 + lr;
#pragma unroll
            for (int nt = 0; nt < 4; nt++) {
                int col = wn + nt * 8 + 2 * lc;
                float b0 = is_enc ? badd[n0 + col]     : 0.f;
                float b1 = is_enc ? badd[n0 + col + 1] : 0.f;
                g_V[(size_t)(m0 + row) * DM + n0 + col]           = acc[mt][nt][0] + b0;
                g_V[(size_t)(m0 + row) * DM + n0 + col + 1]       = acc[mt][nt][1] + b1;
                g_V[(size_t)(m0 + row + 8) * DM + n0 + col]       = acc[mt][nt][2] + b0;
                g_V[(size_t)(m0 + row + 8) * DM + n0 + col + 1]   = acc[mt][nt][3] + b1;
            }
        }
        return;
    }

    // Q/K: stage acc(+bias) to smem, then per-row RMSNorm + RoPE
    float* Es = dsm;   // 128 x PE (fits within GEMM_SMEM)
#pragma unroll
    for (int mt = 0; mt < 4; mt++) {
        int row = wm + mt * 16 + lr;
#pragma unroll
        for (int nt = 0; nt < 4; nt++) {
            int col = wn + nt * 8 + 2 * lc;
            float b0 = is_enc ? badd[n0 + col]     : 0.f;
            float b1 = is_enc ? badd[n0 + col + 1] : 0.f;
            Es[row * PE + col]           = acc[mt][nt][0] + b0;
            Es[row * PE + col + 1]       = acc[mt][nt][1] + b1;
            Es[(row + 8) * PE + col]     = acc[mt][nt][2] + b0;
            Es[(row + 8) * PE + col + 1] = acc[mt][nt][3] + b1;
        }
    }
    __syncthreads();

    const float* gm = is_enc ? (which == 0 ? naq : nak)
                             : (which == 0 ? nq  : nk);
    float* dst = (which == 0) ? g_Q : g_K;

    const int row   = tid >> 1;
    const int cbase = (tid & 1) * 64;
    const int r     = m0 + row;

    float ss = 0.f;
#pragma unroll
    for (int i = 0; i < 64; i += 4) {
        float4 v = *(float4*)&Es[row * PE + cbase + i];
        ss += v.x * v.x + v.y * v.y + v.z * v.z + v.w * v.w;
    }
    ss += __shfl_xor_sync(0xffffffffu, ss, 1);
    float rs = rsqrtf(ss * (1.0f / HD) + 1e-6f);

#pragma unroll
    for (int i = 0; i < 64; i += 4) {
        int d = cbase + i;
        float4 v = *(float4*)&Es[row * PE + d];
        float4 g = *(const float4*)&gm[d];
        float4 c = *(const float4*)&cosb[r * HD + d];
        float4 s = *(const float4*)&sinb[r * HD + d];
        float x0 = v.x * rs * g.x, x1 = v.y * rs * g.y;
        float x2 = v.z * rs * g.z, x3 = v.w * rs * g.w;
        float4 o;
        o.x = x0 * c.x - x1 * s.x;
        o.y = x1 * c.y + x0 * s.y;
        o.z = x2 * c.z - x3 * s.z;
        o.w = x3 * c.w + x2 * s.w;
        *(float4*)&dst[(size_t)r * DM + n0 + d] = o;
    }
}

// ============================================================================
// Fused flash attention, cp.async double-buffered K/V chunks (64 x 128 each).
// One block = (head, 128 q-rows). 8 warps; each warp owns 16 complete rows.
// ============================================================================

#define PQ 132   // Q/K smem pitch (mod 32 == 4)
#define PV 136   // V smem pitch (mod 32 == 8)
#define FLASH_SMEM ((128 * PQ + 2 * 64 * PQ + 2 * 64 * PV) * 4)

__global__ __launch_bounds__(256) void k_flash()
{
    extern __shared__ float sm[];
    float* Qs  = sm;                          // 128 x PQ (tf32, pre-scaled)
    float* KsB = sm + 128 * PQ;               // 2 stages of 64 x PQ
    float* VsB = KsB + 2 * 64 * PQ;           // 2 stages of 64 x PV

    const int tid  = threadIdx.x;
    const int warp = tid >> 5, lane = tid & 31;
    const int lr = lane >> 2, lc = lane & 3;
    const int h  = blockIdx.y;
    const int m0 = blockIdx.x * 128;
    const float scale = 0.088388347648318447f; // 1/sqrt(128)

    for (int i = tid; i < 128 * 32; i += 256) {
        int row = i >> 5, c4 = (i & 31) * 4;
        float4 v = *(const float4*)(g_Q + (size_t)(m0 + row) * DM + h * HD + c4);
        float4 w;
        w.x = to_tf32(v.x * scale); w.y = to_tf32(v.y * scale);
        w.z = to_tf32(v.z * scale); w.w = to_tf32(v.w * scale);
        *(float4*)&Qs[row * PQ + c4] = w;
    }

    float m_r0 = -1e30f, m_r1 = -1e30f;
    float l_r0 = 0.f,    l_r1 = 0.f;
    float O[16][4];
#pragma unroll
    for (int i = 0; i < 16; i++)
#pragma unroll
        for (int j = 0; j < 4; j++) O[i][j] = 0.f;

    const int rb = warp * 16;
    const int srcA = (lane & 28) | (lc >> 1);
    const int srcB = srcA + 2;
    const bool odd = lc & 1;

    auto issue_chunk = [&](int c, int stage) {
        const int s0 = c * 64;
        float* Kd = KsB + stage * 64 * PQ;
        float* Vd = VsB + stage * 64 * PV;
#pragma unroll
        for (int q = 0; q < 8; q++) {
            int idx = tid + q * 256;            // 0..2047
            int row = idx >> 5;                 // 0..63
            int off = (idx & 31) * 4;           // 0..124
            const float* gk = g_K + (size_t)(s0 + row) * DM + h * HD + off;
            const float* gv = g_V + (size_t)(s0 + row) * DM + h * HD + off;
            cp16(&Kd[row * PQ + off], gk);
            cp16(&Vd[row * PV + off], gv);
        }
        CP_COMMIT();
    };

    issue_chunk(0, 0);

    const int NCH = S_ALL / 64;
    for (int c = 0; c < NCH; c++) {
        const int cur = c & 1;
        if (c + 1 < NCH) { issue_chunk(c + 1, cur ^ 1); CP_WAIT1(); }
        else             { CP_WAIT0(); }
        __syncthreads();

        float* Ks = KsB + cur * 64 * PQ;
        float* Vs = VsB + cur * 64 * PV;

        {
            int row = tid >> 2, col = (tid & 3) * 32;
            float* pk = &Ks[row * PQ + col];
            float* pv = &Vs[row * PV + col];
#pragma unroll
            for (int i = 0; i < 32; i++) pk[i] = to_tf32(pk[i]);
#pragma unroll
            for (int i = 0; i < 32; i++) pv[i] = to_tf32(pv[i]);
        }
        __syncthreads();

        float sacc[8][4];
#pragma unroll
        for (int nt = 0; nt < 8; nt++)
#pragma unroll
            for (int r = 0; r < 4; r++) sacc[nt][r] = 0.f;

#pragma unroll
        for (int kk = 0; kk < HD; kk += 8) {
            uint32_t a0 = __float_as_uint(Qs[(rb + lr)     * PQ + kk + lc]);
            uint32_t a1 = __float_as_uint(Qs[(rb + lr + 8) * PQ + kk + lc]);
            uint32_t a2 = __float_as_uint(Qs[(rb + lr)     * PQ + kk + lc + 4]);
            uint32_t a3 = __float_as_uint(Qs[(rb + lr + 8) * PQ + kk + lc + 4]);
#pragma unroll
            for (int nt = 0; nt < 8; nt++) {
                uint32_t b0 = __float_as_uint(Ks[(nt * 8 + lr) * PQ + kk + lc]);
                uint32_t b1 = __float_as_uint(Ks[(nt * 8 + lr) * PQ + kk + lc + 4]);
                asm("mma.sync.aligned.m16n8k8.row.col.f32.tf32.tf32.f32 "
                    "{%0,%1,%2,%3}, {%4,%5,%6,%7}, {%8,%9}, {%0,%1,%2,%3};"
                    : "+f"(sacc[nt][0]), "+f"(sacc[nt][1]),
                      "+f"(sacc[nt][2]), "+f"(sacc[nt][3])
                    : "r"(a0), "r"(a1), "r"(a2), "r"(a3), "r"(b0), "r"(b1));
            }
        }

        float cm0 = -1e30f, cm1 = -1e30f;
#pragma unroll
        for (int nt = 0; nt < 8; nt++) {
            cm0 = fmaxf(cm0, fmaxf(sacc[nt][0], sacc[nt][1]));
            cm1 = fmaxf(cm1, fmaxf(sacc[nt][2], sacc[nt][3]));
        }
        cm0 = fmaxf(cm0, __shfl_xor_sync(0xffffffffu, cm0, 1));
        cm0 = fmaxf(cm0, __shfl_xor_sync(0xffffffffu, cm0, 2));
        cm1 = fmaxf(cm1, __shfl_xor_sync(0xffffffffu, cm1, 1));
        cm1 = fmaxf(cm1, __shfl_xor_sync(0xffffffffu, cm1, 2));

        float mn0 = fmaxf(m_r0, cm0), mn1 = fmaxf(m_r1, cm1);
        float al0 = __expf(m_r0 - mn0), al1 = __expf(m_r1 - mn1);
        m_r0 = mn0; m_r1 = mn1;

        float cs0 = 0.f, cs1 = 0.f;
#pragma unroll
        for (int nt = 0; nt < 8; nt++) {
            float p0 = to_tf32(__expf(sacc[nt][0] - mn0));
            float p1 = to_tf32(__expf(sacc[nt][1] - mn0));
            float p2 = to_tf32(__expf(sacc[nt][2] - mn1));
            float p3 = to_tf32(__expf(sacc[nt][3] - mn1));
            sacc[nt][0] = p0; sacc[nt][1] = p1; sacc[nt][2] = p2; sacc[nt][3] = p3;
            cs0 += p0 + p1; cs1 += p2 + p3;
        }
        cs0 += __shfl_xor_sync(0xffffffffu, cs0, 1);
        cs0 += __shfl_xor_sync(0xffffffffu, cs0, 2);
        cs1 += __shfl_xor_sync(0xffffffffu, cs1, 1);
        cs1 += __shfl_xor_sync(0xffffffffu, cs1, 2);
        l_r0 = l_r0 * al0 + cs0;
        l_r1 = l_r1 * al1 + cs1;

#pragma unroll
        for (int nt2 = 0; nt2 < 16; nt2++) {
            O[nt2][0] *= al0; O[nt2][1] *= al0;
            O[nt2][2] *= al1; O[nt2][3] *= al1;
        }

#pragma unroll
        for (int ks = 0; ks < 8; ks++) {
            float c0 = sacc[ks][0], c1 = sacc[ks][1];
            float c2 = sacc[ks][2], c3 = sacc[ks][3];
            float v00 = __shfl_sync(0xffffffffu, c0, srcA);
            float v01 = __shfl_sync(0xffffffffu, c1, srcA);
            float v10 = __shfl_sync(0xffffffffu, c2, srcA);
            float v11 = __shfl_sync(0xffffffffu, c3, srcA);
            float w00 = __shfl_sync(0xffffffffu, c0, srcB);
            float w01 = __shfl_sync(0xffffffffu, c1, srcB);
            float w10 = __shfl_sync(0xffffffffu, c2, srcB);
            float w11 = __shfl_sync(0xffffffffu, c3, srcB);
            uint32_t a0 = __float_as_uint(odd ? v01 : v00);
            uint32_t a1 = __float_as_uint(odd ? v11 : v10);
            uint32_t a2 = __float_as_uint(odd ? w01 : w00);
            uint32_t a3 = __float_as_uint(odd ? w11 : w10);
#pragma unroll
            for (int nt2 = 0; nt2 < 16; nt2++) {
                uint32_t b0 = __float_as_uint(Vs[(ks * 8 + lc)     * PV + nt2 * 8 + lr]);
                uint32_t b1 = __float_as_uint(Vs[(ks * 8 + lc + 4) * PV + nt2 * 8 + lr]);
                asm("mma.sync.aligned.m16n8k8.row.col.f32.tf32.tf32.f32 "
                    "{%0,%1,%2,%3}, {%4,%5,%6,%7}, {%8,%9}, {%0,%1,%2,%3};"
                    : "+f"(O[nt2][0]), "+f"(O[nt2][1]),
                      "+f"(O[nt2][2]), "+f"(O[nt2][3])
                    : "r"(a0), "r"(a1), "r"(a2), "r"(a3), "r"(b0), "r"(b1));
            }
        }
        __syncthreads();
    }

    float i0 = 1.0f / l_r0, i1 = 1.0f / l_r1;
    const int row0 = m0 + rb + lr;
#pragma unroll
    for (int nt2 = 0; nt2 < 16; nt2++) {
        int col = h * HD + nt2 * 8 + 2 * lc;
        g_O[(size_t)row0 * DM + col]           = O[nt2][0] * i0;
        g_O[(size_t)row0 * DM + col + 1]       = O[nt2][1] * i0;
        g_O[(size_t)(row0 + 8) * DM + col]     = O[nt2][2] * i1;
        g_O[(size_t)(row0 + 8) * DM + col + 1] = O[nt2][3] * i1;
    }
}

// ---- output projections ------------------------------------------------------
__global__ __launch_bounds__(256) void k_outproj(
    const float* __restrict__ w_out, const float* __restrict__ b_out,
    const float* __restrict__ w_ao,  const float* __restrict__ b_ao,
    float* __restrict__ outbuf)
{
    const int n0 = blockIdx.x * 128;
    const int m0 = blockIdx.y * 128;
    const bool is_enc = (m0 < STXT);
    const float* B    = (is_enc ? w_ao : w_out) + n0;
    const float* bias = (is_enc ? b_ao : b_out) + n0;
    float* out = is_enc ? (outbuf + (size_t)SIMG * DM + (size_t)m0 * DM)
                        : (outbuf + (size_t)(m0 - STXT) * DM);

    float acc[4][4][4];
    gemm_core(g_O + (size_t)m0 * DM, DM, B, DM, DM, acc);

    const int tid  = threadIdx.x;
    const int warp = tid >> 5, lane = tid & 31;
    const int wm = (warp >> 2) * 64;
    const int wn = (warp & 3)  * 32;
    const int lr = lane >> 2, lc = lane & 3;

#pragma unroll
    for (int mt = 0; mt < 4; mt++) {
        int row = wm + mt * 16 + lr;
#pragma unroll
        for (int nt = 0; nt < 4; nt++) {
            int col = wn + nt * 8 + 2 * lc;
            float b0 = bias[col];
            float b1 = bias[col + 1];
            out[(size_t)row * DM + n0 + col]           = acc[mt][nt][0] + b0;
            out[(size_t)row * DM + n0 + col + 1]       = acc[mt][nt][1] + b1;
            out[(size_t)(row + 8) * DM + n0 + col]     = acc[mt][nt][2] + b0;
            out[(size_t)(row + 8) * DM + n0 + col + 1] = acc[mt][nt][3] + b1;
        }
    }
}

// ============================================================================
extern "C" void kernel_launch(void* const* d_in, const int* in_sizes, int n_in,
                              void* d_out, int out_size)
{
    const float* hid  = (const float*)d_in[0];
    const float* enc  = (const float*)d_in[1];
    const float* cosb = (const float*)d_in[2];
    const float* sinb = (const float*)d_in[3];
    const float* wq   = (const float*)d_in[4];
    const float* wk   = (const float*)d_in[5];
    const float* wv   = (const float*)d_in[6];
    const float* wqa  = (const float*)d_in[7];
    const float* wka  = (const float*)d_in[8];
    const float* wva  = (const float*)d_in[9];
    const float* bqa  = (const float*)d_in[10];
    const float* bka  = (const float*)d_in[11];
    const float* bva  = (const float*)d_in[12];
    const float* nq   = (const float*)d_in[13];
    const float* nk   = (const float*)d_in[14];
    const float* naq  = (const float*)d_in[15];
    const float* nak  = (const float*)d_in[16];
    const float* wout = (const float*)d_in[17];
    const float* bout = (const float*)d_in[18];
    const float* wao  = (const float*)d_in[19];
    const float* bao  = (const float*)d_in[20];
    float* out = (float*)d_out;

    cudaFuncSetAttribute(k_qkv,     cudaFuncAttributeMaxDynamicSharedMemorySize, GEMM_SMEM);
    cudaFuncSetAttribute(k_outproj, cudaFuncAttributeMaxDynamicSharedMemorySize, GEMM_SMEM);
    cudaFuncSetAttribute(k_flash,   cudaFuncAttributeMaxDynamicSharedMemorySize, FLASH_SMEM);

    dim3 qkv_grid(DM / 128, S_ALL / 128, 3);        // 24 x 18 x 3
    k_qkv<<<qkv_grid, 256, GEMM_SMEM>>>(hid, enc, wq, wk, wv,
                                        wqa, wka, wva, bqa, bka, bva,
                                        nq, naq, nk, nak, cosb, sinb);

    dim3 fl_grid(S_ALL / 128, NH);                  // 18 x 24
    k_flash<<<fl_grid, 256, FLASH_SMEM>>>();

    dim3 gemm_grid(DM / 128, S_ALL / 128);          // 24 x 18
    k_outproj<<<gemm_grid, 256, GEMM_SMEM>>>(wout, bout, wao, bao, out);
}

// round 8
// speedup vs baseline: 1.3612x; 1.0678x over previous
#include <cuda_runtime.h>
#include <math.h>
#include <stdint.h>

#define S_ALL 2304
#define STXT  256
#define SIMG  2048
#define DM    3072
#define NH    24
#define HD    128

// ---------------- scratch (static device globals; no runtime allocation) ----
// All four buffers hold tf32-rounded values (rounded at producer).
__device__ float g_Q [S_ALL * DM];   // pre-scaled by 1/sqrt(128)
__device__ float g_K [S_ALL * DM];
__device__ float g_V [S_ALL * DM];
__device__ float g_O [S_ALL * DM];

__device__ __forceinline__ float to_tf32(float x) {
    uint32_t u;
    asm("cvt.rna.tf32.f32 %0, %1;" : "=r"(u) : "f"(x));
    return __uint_as_float(u);
}
__device__ __forceinline__ uint32_t to_tf32u(float x) {
    uint32_t u;
    asm("cvt.rna.tf32.f32 %0, %1;" : "=r"(u) : "f"(x));
    return u;
}

__device__ __forceinline__ void cp16(float* dst, const float* src) {
    uint32_t s = (uint32_t)__cvta_generic_to_shared(dst);
    asm volatile("cp.async.cg.shared.global [%0], [%1], 16;" :: "r"(s), "l"(src));
}
#define CP_COMMIT() asm volatile("cp.async.commit_group;")
#define CP_WAIT2()  asm volatile("cp.async.wait_group 2;")
#define CP_WAIT1()  asm volatile("cp.async.wait_group 1;")
#define CP_WAIT0()  asm volatile("cp.async.wait_group 0;")

// ============================================================================
// tf32 tensor-core GEMM core: 128x128 block tile, 8 warps (2x4), warp tile
// 64x32, k-step 32, 3-stage cp.async pipeline. CVTA: round A frags (false if
// A was pre-rounded by its producer). B (weights) always rounded at frag load.
// ============================================================================

#define PA 36
#define PB 136
#define PE 132
#define NSTG 3
#define GEMM_SMEM ((NSTG * 128 * PA + NSTG * 32 * PB) * 4)

template<bool CVTA>
__device__ __forceinline__ void gemm_core(
    const float* __restrict__ A, int lda,
    const float* __restrict__ B, int ldb,
    int K, float acc[4][4][4])
{
    extern __shared__ float dsm[];
    float* AsB = dsm;                       // NSTG stages of 128*PA
    float* BsB = dsm + NSTG * 128 * PA;     // NSTG stages of 32*PB

    const int tid  = threadIdx.x;
    const int warp = tid >> 5, lane = tid & 31;
    const int wm = (warp >> 2) * 64;
    const int wn = (warp & 3)  * 32;
    const int lr = lane >> 2, lc = lane & 3;

    const int am = tid >> 1, ak = (tid & 1) * 16;
    const int bk = tid >> 3, bn = (tid & 7) * 16;

#pragma unroll
    for (int mt = 0; mt < 4; mt++)
#pragma unroll
        for (int nt = 0; nt < 4; nt++)
#pragma unroll
            for (int r = 0; r < 4; r++) acc[mt][nt][r] = 0.f;

    auto issue = [&](int k0, int stage) {
        const float* Ag = A + (size_t)am * lda + k0 + ak;
        float* Ad = AsB + stage * 128 * PA + am * PA + ak;
#pragma unroll
        for (int i = 0; i < 4; i++) cp16(Ad + i * 4, Ag + i * 4);
        const float* Bg = B + (size_t)(k0 + bk) * ldb + bn;
        float* Bd = BsB + stage * 32 * PB + bk * PB + bn;
#pragma unroll
        for (int i = 0; i < 4; i++) cp16(Bd + i * 4, Bg + i * 4);
        CP_COMMIT();
    };

    const int ntile = K / 32;
    issue(0, 0);
    issue(32, 1);

    for (int t = 0; t < ntile; t++) {
        const int cur = t % NSTG;
        if (t + 2 < ntile) { issue((t + 2) * 32, (t + 2) % NSTG); CP_WAIT2(); }
        else if (t + 1 < ntile) { CP_WAIT1(); }
        else { CP_WAIT0(); }
        __syncthreads();

        const float* As = AsB + cur * 128 * PA;
        const float* Bs = BsB + cur * 32 * PB;

#pragma unroll
        for (int kk = 0; kk < 32; kk += 8) {
            uint32_t a[4][4], b[4][2];
#pragma unroll
            for (int mt = 0; mt < 4; mt++) {
                int rb = wm + mt * 16;
                float x0 = As[(rb + lr)     * PA + kk + lc];
                float x1 = As[(rb + lr + 8) * PA + kk + lc];
                float x2 = As[(rb + lr)     * PA + kk + lc + 4];
                float x3 = As[(rb + lr + 8) * PA + kk + lc + 4];
                a[mt][0] = CVTA ? to_tf32u(x0) : __float_as_uint(x0);
                a[mt][1] = CVTA ? to_tf32u(x1) : __float_as_uint(x1);
                a[mt][2] = CVTA ? to_tf32u(x2) : __float_as_uint(x2);
                a[mt][3] = CVTA ? to_tf32u(x3) : __float_as_uint(x3);
            }
#pragma unroll
            for (int nt = 0; nt < 4; nt++) {
                int cb = wn + nt * 8;
                b[nt][0] = to_tf32u(Bs[(kk + lc)     * PB + cb + lr]);
                b[nt][1] = to_tf32u(Bs[(kk + lc + 4) * PB + cb + lr]);
            }
#pragma unroll
            for (int mt = 0; mt < 4; mt++)
#pragma unroll
                for (int nt = 0; nt < 4; nt++) {
                    asm("mma.sync.aligned.m16n8k8.row.col.f32.tf32.tf32.f32 "
                        "{%0,%1,%2,%3}, {%4,%5,%6,%7}, {%8,%9}, {%0,%1,%2,%3};"
                        : "+f"(acc[mt][nt][0]), "+f"(acc[mt][nt][1]),
                          "+f"(acc[mt][nt][2]), "+f"(acc[mt][nt][3])
                        : "r"(a[mt][0]), "r"(a[mt][1]), "r"(a[mt][2]), "r"(a[mt][3]),
                          "r"(b[nt][0]), "r"(b[nt][1]));
                }
        }
        __syncthreads();
    }
}

// ---- QKV projection + fused RMSNorm/RoPE epilogue (tf32-rounded outputs) ---
__global__ __launch_bounds__(256) void k_qkv(
    const float* __restrict__ hid, const float* __restrict__ enc,
    const float* __restrict__ wq,  const float* __restrict__ wk,
    const float* __restrict__ wv,
    const float* __restrict__ wqa, const float* __restrict__ wka,
    const float* __restrict__ wva,
    const float* __restrict__ bqa, const float* __restrict__ bka,
    const float* __restrict__ bva,
    const float* __restrict__ nq,  const float* __restrict__ naq,
    const float* __restrict__ nk,  const float* __restrict__ nak,
    const float* __restrict__ cosb, const float* __restrict__ sinb)
{
    extern __shared__ float dsm[];
    const int which = blockIdx.z;
    const float* W    = (which == 0) ? wq  : (which == 1) ? wk  : wv;
    const float* Wadd = (which == 0) ? wqa : (which == 1) ? wka : wva;
    const float* badd = (which == 0) ? bqa : (which == 1) ? bka : bva;

    const int n0 = blockIdx.x * 128;
    const int m0 = blockIdx.y * 128;
    const bool is_enc = (m0 < STXT);
    const float* A = is_enc ? (enc + (size_t)m0 * DM)
                            : (hid + (size_t)(m0 - STXT) * DM);
    const float* B = (is_enc ? Wadd : W) + n0;

    float acc[4][4][4];
    gemm_core<true>(A, DM, B, DM, DM, acc);

    const int tid  = threadIdx.x;
    const int warp = tid >> 5, lane = tid & 31;
    const int wm = (warp >> 2) * 64;
    const int wn = (warp & 3)  * 32;
    const int lr = lane >> 2, lc = lane & 3;

    if (which == 2) {
#pragma unroll
        for (int mt = 0; mt < 4; mt++) {
            int row = wm + mt * 16 + lr;
#pragma unroll
            for (int nt = 0; nt < 4; nt++) {
                int col = wn + nt * 8 + 2 * lc;
                float b0 = is_enc ? badd[n0 + col]     : 0.f;
                float b1 = is_enc ? badd[n0 + col + 1] : 0.f;
                g_V[(size_t)(m0 + row) * DM + n0 + col]         = to_tf32(acc[mt][nt][0] + b0);
                g_V[(size_t)(m0 + row) * DM + n0 + col + 1]     = to_tf32(acc[mt][nt][1] + b1);
                g_V[(size_t)(m0 + row + 8) * DM + n0 + col]     = to_tf32(acc[mt][nt][2] + b0);
                g_V[(size_t)(m0 + row + 8) * DM + n0 + col + 1] = to_tf32(acc[mt][nt][3] + b1);
            }
        }
        return;
    }

    // Q/K: stage acc(+bias) to smem, per-row RMSNorm + RoPE, round, store
    float* Es = dsm;   // 128 x PE
#pragma unroll
    for (int mt = 0; mt < 4; mt++) {
        int row = wm + mt * 16 + lr;
#pragma unroll
        for (int nt = 0; nt < 4; nt++) {
            int col = wn + nt * 8 + 2 * lc;
            float b0 = is_enc ? badd[n0 + col]     : 0.f;
            float b1 = is_enc ? badd[n0 + col + 1] : 0.f;
            Es[row * PE + col]           = acc[mt][nt][0] + b0;
            Es[row * PE + col + 1]       = acc[mt][nt][1] + b1;
            Es[(row + 8) * PE + col]     = acc[mt][nt][2] + b0;
            Es[(row + 8) * PE + col + 1] = acc[mt][nt][3] + b1;
        }
    }
    __syncthreads();

    const float* gm = is_enc ? (which == 0 ? naq : nak)
                             : (which == 0 ? nq  : nk);
    float* dst = (which == 0) ? g_Q : g_K;
    const float mult = (which == 0) ? 0.088388347648318447f : 1.0f; // fold 1/sqrt(128) into Q

    const int row   = tid >> 1;
    const int cbase = (tid & 1) * 64;
    const int r     = m0 + row;

    float ss = 0.f;
#pragma unroll
    for (int i = 0; i < 64; i += 4) {
        float4 v = *(float4*)&Es[row * PE + cbase + i];
        ss += v.x * v.x + v.y * v.y + v.z * v.z + v.w * v.w;
    }
    ss += __shfl_xor_sync(0xffffffffu, ss, 1);
    float rs = rsqrtf(ss * (1.0f / HD) + 1e-6f);

#pragma unroll
    for (int i = 0; i < 64; i += 4) {
        int d = cbase + i;
        float4 v = *(float4*)&Es[row * PE + d];
        float4 g = *(const float4*)&gm[d];
        float4 c = *(const float4*)&cosb[r * HD + d];
        float4 s = *(const float4*)&sinb[r * HD + d];
        float x0 = v.x * rs * g.x, x1 = v.y * rs * g.y;
        float x2 = v.z * rs * g.z, x3 = v.w * rs * g.w;
        float4 o;
        o.x = to_tf32((x0 * c.x - x1 * s.x) * mult);
        o.y = to_tf32((x1 * c.y + x0 * s.y) * mult);
        o.z = to_tf32((x2 * c.z - x3 * s.z) * mult);
        o.w = to_tf32((x3 * c.w + x2 * s.w) * mult);
        *(float4*)&dst[(size_t)r * DM + n0 + d] = o;
    }
}

// ============================================================================
// Fused flash attention. Inputs already tf32-rounded (Q pre-scaled), so no
// per-chunk conversion pass. Q loaded via cp.async in chunk-0's commit group.
// ============================================================================

#define PQ 132
#define PV 136
#define FLASH_SMEM ((128 * PQ + 2 * 64 * PQ + 2 * 64 * PV) * 4)

__global__ __launch_bounds__(256) void k_flash()
{
    extern __shared__ float sm[];
    float* Qs  = sm;                          // 128 x PQ
    float* KsB = sm + 128 * PQ;               // 2 stages of 64 x PQ
    float* VsB = KsB + 2 * 64 * PQ;           // 2 stages of 64 x PV

    const int tid  = threadIdx.x;
    const int warp = tid >> 5, lane = tid & 31;
    const int lr = lane >> 2, lc = lane & 3;
    const int h  = blockIdx.y;
    const int m0 = blockIdx.x * 128;

    auto issue_chunk = [&](int c, int stage) {
        const int s0 = c * 64;
        float* Kd = KsB + stage * 64 * PQ;
        float* Vd = VsB + stage * 64 * PV;
#pragma unroll
        for (int q = 0; q < 8; q++) {
            int idx = tid + q * 256;
            int row = idx >> 5;
            int off = (idx & 31) * 4;
            cp16(&Kd[row * PQ + off], g_K + (size_t)(s0 + row) * DM + h * HD + off);
            cp16(&Vd[row * PV + off], g_V + (size_t)(s0 + row) * DM + h * HD + off);
        }
        CP_COMMIT();
    };

    // Q tile via cp.async, committed together with chunk 0
#pragma unroll
    for (int q = 0; q < 16; q++) {
        int idx = tid + q * 256;                // 0..4095
        int row = idx >> 5;                     // 0..127
        int off = (idx & 31) * 4;
        cp16(&Qs[row * PQ + off], g_Q + (size_t)(m0 + row) * DM + h * HD + off);
    }
    issue_chunk(0, 0);

    float m_r0 = -1e30f, m_r1 = -1e30f;
    float l_r0 = 0.f,    l_r1 = 0.f;
    float O[16][4];
#pragma unroll
    for (int i = 0; i < 16; i++)
#pragma unroll
        for (int j = 0; j < 4; j++) O[i][j] = 0.f;

    const int rb = warp * 16;
    const int srcA = (lane & 28) | (lc >> 1);
    const int srcB = srcA + 2;
    const bool odd = lc & 1;

    const int NCH = S_ALL / 64;
    for (int c = 0; c < NCH; c++) {
        const int cur = c & 1;
        if (c + 1 < NCH) { issue_chunk(c + 1, cur ^ 1); CP_WAIT1(); }
        else             { CP_WAIT0(); }
        __syncthreads();

        const float* Ks = KsB + cur * 64 * PQ;
        const float* Vs = VsB + cur * 64 * PV;

        float sacc[8][4];
#pragma unroll
        for (int nt = 0; nt < 8; nt++)
#pragma unroll
            for (int r = 0; r < 4; r++) sacc[nt][r] = 0.f;

#pragma unroll
        for (int kk = 0; kk < HD; kk += 8) {
            uint32_t a0 = __float_as_uint(Qs[(rb + lr)     * PQ + kk + lc]);
            uint32_t a1 = __float_as_uint(Qs[(rb + lr + 8) * PQ + kk + lc]);
            uint32_t a2 = __float_as_uint(Qs[(rb + lr)     * PQ + kk + lc + 4]);
            uint32_t a3 = __float_as_uint(Qs[(rb + lr + 8) * PQ + kk + lc + 4]);
#pragma unroll
            for (int nt = 0; nt < 8; nt++) {
                uint32_t b0 = __float_as_uint(Ks[(nt * 8 + lr) * PQ + kk + lc]);
                uint32_t b1 = __float_as_uint(Ks[(nt * 8 + lr) * PQ + kk + lc + 4]);
                asm("mma.sync.aligned.m16n8k8.row.col.f32.tf32.tf32.f32 "
                    "{%0,%1,%2,%3}, {%4,%5,%6,%7}, {%8,%9}, {%0,%1,%2,%3};"
                    : "+f"(sacc[nt][0]), "+f"(sacc[nt][1]),
                      "+f"(sacc[nt][2]), "+f"(sacc[nt][3])
                    : "r"(a0), "r"(a1), "r"(a2), "r"(a3), "r"(b0), "r"(b1));
            }
        }

        float cm0 = -1e30f, cm1 = -1e30f;
#pragma unroll
        for (int nt = 0; nt < 8; nt++) {
            cm0 = fmaxf(cm0, fmaxf(sacc[nt][0], sacc[nt][1]));
            cm1 = fmaxf(cm1, fmaxf(sacc[nt][2], sacc[nt][3]));
        }
        cm0 = fmaxf(cm0, __shfl_xor_sync(0xffffffffu, cm0, 1));
        cm0 = fmaxf(cm0, __shfl_xor_sync(0xffffffffu, cm0, 2));
        cm1 = fmaxf(cm1, __shfl_xor_sync(0xffffffffu, cm1, 1));
        cm1 = fmaxf(cm1, __shfl_xor_sync(0xffffffffu, cm1, 2));

        float mn0 = fmaxf(m_r0, cm0), mn1 = fmaxf(m_r1, cm1);
        float al0 = __expf(m_r0 - mn0), al1 = __expf(m_r1 - mn1);
        m_r0 = mn0; m_r1 = mn1;

        float cs0 = 0.f, cs1 = 0.f;
#pragma unroll
        for (int nt = 0; nt < 8; nt++) {
            float p0 = to_tf32(__expf(sacc[nt][0] - mn0));
            float p1 = to_tf32(__expf(sacc[nt][1] - mn0));
            float p2 = to_tf32(__expf(sacc[nt][2] - mn1));
            float p3 = to_tf32(__expf(sacc[nt][3] - mn1));
            sacc[nt][0] = p0; sacc[nt][1] = p1; sacc[nt][2] = p2; sacc[nt][3] = p3;
            cs0 += p0 + p1; cs1 += p2 + p3;
        }
        cs0 += __shfl_xor_sync(0xffffffffu, cs0, 1);
        cs0 += __shfl_xor_sync(0xffffffffu, cs0, 2);
        cs1 += __shfl_xor_sync(0xffffffffu, cs1, 1);
        cs1 += __shfl_xor_sync(0xffffffffu, cs1, 2);
        l_r0 = l_r0 * al0 + cs0;
        l_r1 = l_r1 * al1 + cs1;

#pragma unroll
        for (int nt2 = 0; nt2 < 16; nt2++) {
            O[nt2][0] *= al0; O[nt2][1] *= al0;
            O[nt2][2] *= al1; O[nt2][3] *= al1;
        }

#pragma unroll
        for (int ks = 0; ks < 8; ks++) {
            float c0 = sacc[ks][0], c1 = sacc[ks][1];
            float c2 = sacc[ks][2], c3 = sacc[ks][3];
            float v00 = __shfl_sync(0xffffffffu, c0, srcA);
            float v01 = __shfl_sync(0xffffffffu, c1, srcA);
            float v10 = __shfl_sync(0xffffffffu, c2, srcA);
            float v11 = __shfl_sync(0xffffffffu, c3, srcA);
            float w00 = __shfl_sync(0xffffffffu, c0, srcB);
            float w01 = __shfl_sync(0xffffffffu, c1, srcB);
            float w10 = __shfl_sync(0xffffffffu, c2, srcB);
            float w11 = __shfl_sync(0xffffffffu, c3, srcB);
            uint32_t a0 = __float_as_uint(odd ? v01 : v00);
            uint32_t a1 = __float_as_uint(odd ? v11 : v10);
            uint32_t a2 = __float_as_uint(odd ? w01 : w00);
            uint32_t a3 = __float_as_uint(odd ? w11 : w10);
#pragma unroll
            for (int nt2 = 0; nt2 < 16; nt2++) {
                uint32_t b0 = __float_as_uint(Vs[(ks * 8 + lc)     * PV + nt2 * 8 + lr]);
                uint32_t b1 = __float_as_uint(Vs[(ks * 8 + lc + 4) * PV + nt2 * 8 + lr]);
                asm("mma.sync.aligned.m16n8k8.row.col.f32.tf32.tf32.f32 "
                    "{%0,%1,%2,%3}, {%4,%5,%6,%7}, {%8,%9}, {%0,%1,%2,%3};"
                    : "+f"(O[nt2][0]), "+f"(O[nt2][1]),
                      "+f"(O[nt2][2]), "+f"(O[nt2][3])
                    : "r"(a0), "r"(a1), "r"(a2), "r"(a3), "r"(b0), "r"(b1));
            }
        }
        __syncthreads();
    }

    // epilogue: write O tf32-rounded (consumed by outproj with CVTA=false)
    float i0 = 1.0f / l_r0, i1 = 1.0f / l_r1;
    const int row0 = m0 + rb + lr;
#pragma unroll
    for (int nt2 = 0; nt2 < 16; nt2++) {
        int col = h * HD + nt2 * 8 + 2 * lc;
        g_O[(size_t)row0 * DM + col]           = to_tf32(O[nt2][0] * i0);
        g_O[(size_t)row0 * DM + col + 1]       = to_tf32(O[nt2][1] * i0);
        g_O[(size_t)(row0 + 8) * DM + col]     = to_tf32(O[nt2][2] * i1);
        g_O[(size_t)(row0 + 8) * DM + col + 1] = to_tf32(O[nt2][3] * i1);
    }
}

// ---- output projections ------------------------------------------------------
__global__ __launch_bounds__(256) void k_outproj(
    const float* __restrict__ w_out, const float* __restrict__ b_out,
    const float* __restrict__ w_ao,  const float* __restrict__ b_ao,
    float* __restrict__ outbuf)
{
    const int n0 = blockIdx.x * 128;
    const int m0 = blockIdx.y * 128;
    const bool is_enc = (m0 < STXT);
    const float* B    = (is_enc ? w_ao : w_out) + n0;
    const float* bias = (is_enc ? b_ao : b_out) + n0;
    float* out = is_enc ? (outbuf + (size_t)SIMG * DM + (size_t)m0 * DM)
                        : (outbuf + (size_t)(m0 - STXT) * DM);

    float acc[4][4][4];
    gemm_core<false>(g_O + (size_t)m0 * DM, DM, B, DM, DM, acc);

    const int tid  = threadIdx.x;
    const int warp = tid >> 5, lane = tid & 31;
    const int wm = (warp >> 2) * 64;
    const int wn = (warp & 3)  * 32;
    const int lr = lane >> 2, lc = lane & 3;

#pragma unroll
    for (int mt = 0; mt < 4; mt++) {
        int row = wm + mt * 16 + lr;
#pragma unroll
        for (int nt = 0; nt < 4; nt++) {
            int col = wn + nt * 8 + 2 * lc;
            float b0 = bias[col];
            float b1 = bias[col + 1];
            out[(size_t)row * DM + n0 + col]           = acc[mt][nt][0] + b0;
            out[(size_t)row * DM + n0 + col + 1]       = acc[mt][nt][1] + b1;
            out[(size_t)(row + 8) * DM + n0 + col]     = acc[mt][nt][2] + b0;
            out[(size_t)(row + 8) * DM + n0 + col + 1] = acc[mt][nt][3] + b1;
        }
    }
}

// ============================================================================
extern "C" void kernel_launch(void* const* d_in, const int* in_sizes, int n_in,
                              void* d_out, int out_size)
{
    const float* hid  = (const float*)d_in[0];
    const float* enc  = (const float*)d_in[1];
    const float* cosb = (const float*)d_in[2];
    const float* sinb = (const float*)d_in[3];
    const float* wq   = (const float*)d_in[4];
    const float* wk   = (const float*)d_in[5];
    const float* wv   = (const float*)d_in[6];
    const float* wqa  = (const float*)d_in[7];
    const float* wka  = (const float*)d_in[8];
    const float* wva  = (const float*)d_in[9];
    const float* bqa  = (const float*)d_in[10];
    const float* bka  = (const float*)d_in[11];
    const float* bva  = (const float*)d_in[12];
    const float* nq   = (const float*)d_in[13];
    const float* nk   = (const float*)d_in[14];
    const float* naq  = (const float*)d_in[15];
    const float* nak  = (const float*)d_in[16];
    const float* wout = (const float*)d_in[17];
    const float* bout = (const float*)d_in[18];
    const float* wao  = (const float*)d_in[19];
    const float* bao  = (const float*)d_in[20];
    float* out = (float*)d_out;

    cudaFuncSetAttribute(k_qkv,     cudaFuncAttributeMaxDynamicSharedMemorySize, GEMM_SMEM);
    cudaFuncSetAttribute(k_outproj, cudaFuncAttributeMaxDynamicSharedMemorySize, GEMM_SMEM);
    cudaFuncSetAttribute(k_flash,   cudaFuncAttributeMaxDynamicSharedMemorySize, FLASH_SMEM);

    dim3 qkv_grid(DM / 128, S_ALL / 128, 3);        // 24 x 18 x 3
    k_qkv<<<qkv_grid, 256, GEMM_SMEM>>>(hid, enc, wq, wk, wv,
                                        wqa, wka, wva, bqa, bka, bva,
                                        nq, naq, nk, nak, cosb, sinb);

    dim3 fl_grid(S_ALL / 128, NH);                  // 18 x 24
    k_flash<<<fl_grid, 256, FLASH_SMEM>>>();

    dim3 gemm_grid(DM / 128, S_ALL / 128);          // 24 x 18
    k_outproj<<<gemm_grid, 256, GEMM_SMEM>>>(wout, bout, wao, bao, out);
}